// round 1
// baseline (speedup 1.0000x reference)
#include <cuda_runtime.h>
#include <math.h>

#define NATOMS 8192
#define HID    256
#define MBOND  16
#define NHEADS 8
#define HD     32
#define H3     768
#define FFD    1024

// ---------------- scratch (static device globals; no allocs allowed) ----------
__device__ float g_qkv[NATOMS * H3];          // 25 MB
__device__ float g_o  [NATOMS * HID];         // 8 MB   attention output (nhd)
__device__ float g_x1 [NATOMS * HID];         // 8 MB   after LN1
__device__ float g_t1 [NATOMS * HID];         // 8 MB   x1 @ na_w1_top + na_b1
__device__ float g_h  [NATOMS * MBOND * HID]; // 134 MB neighbor MLP hidden
__device__ float g_x2 [NATOMS * HID];         // 8 MB   after neighbor message
__device__ float g_ff [NATOMS * FFD];         // 33 MB  FF hidden
__device__ float g_t4 [NATOMS * HID];         // 8 MB   generic [N,H] temp

// ---------------- generic tiled SGEMM: C = op(A@B (+bias) (+aux[r>>4])) -------
// A [M,K] row-major, B [K,N] row-major, C [M,N]. BM=BN=64, BK=16, 256 thr, 4x4.
template <bool RELU, bool AUX16>
__global__ __launch_bounds__(256) void sgemm_kernel(
    const float* __restrict__ A, const float* __restrict__ B,
    const float* __restrict__ bias, const float* __restrict__ aux,
    float* __restrict__ C, int Mdim, int Ndim, int Kdim)
{
    __shared__ float As[16][68];   // padded: transposed A tile [k][m]
    __shared__ float Bs[16][64];   // [k][n]

    const int tid = threadIdx.x;
    const int tx = tid & 15, ty = tid >> 4;
    const int rowBase = blockIdx.y * 64;
    const int colBase = blockIdx.x * 64;

    const int ar = tid >> 2;            // 0..63
    const int ak = (tid & 3) << 2;      // 0,4,8,12
    const int bk = tid >> 4;            // 0..15
    const int bc = (tid & 15) << 2;     // 0..60

    const float* Aptr = A + (size_t)(rowBase + ar) * Kdim + ak;
    const float* Bptr = B + (size_t)bk * Ndim + colBase + bc;

    float acc[4][4] = {};

    for (int k0 = 0; k0 < Kdim; k0 += 16) {
        float4 av = *(const float4*)(Aptr + k0);
        As[ak + 0][ar] = av.x; As[ak + 1][ar] = av.y;
        As[ak + 2][ar] = av.z; As[ak + 3][ar] = av.w;
        float4 bv = *(const float4*)(Bptr + (size_t)k0 * Ndim);
        *(float4*)&Bs[bk][bc] = bv;
        __syncthreads();

#pragma unroll
        for (int k = 0; k < 16; k++) {
            float4 a = *(const float4*)&As[k][ty << 2];
            float4 b = *(const float4*)&Bs[k][tx << 2];
            acc[0][0] += a.x * b.x; acc[0][1] += a.x * b.y; acc[0][2] += a.x * b.z; acc[0][3] += a.x * b.w;
            acc[1][0] += a.y * b.x; acc[1][1] += a.y * b.y; acc[1][2] += a.y * b.z; acc[1][3] += a.y * b.w;
            acc[2][0] += a.z * b.x; acc[2][1] += a.z * b.y; acc[2][2] += a.z * b.z; acc[2][3] += a.z * b.w;
            acc[3][0] += a.w * b.x; acc[3][1] += a.w * b.y; acc[3][2] += a.w * b.z; acc[3][3] += a.w * b.w;
        }
        __syncthreads();
    }

#pragma unroll
    for (int i = 0; i < 4; i++) {
        int r = rowBase + (ty << 2) + i;
        int c = colBase + (tx << 2);
        float4 v;
        v.x = acc[i][0]; v.y = acc[i][1]; v.z = acc[i][2]; v.w = acc[i][3];
        if (bias) {
            v.x += bias[c]; v.y += bias[c + 1]; v.z += bias[c + 2]; v.w += bias[c + 3];
        }
        if (AUX16) {
            const float* ap = aux + (size_t)(r >> 4) * Ndim + c;
            v.x += ap[0]; v.y += ap[1]; v.z += ap[2]; v.w += ap[3];
        }
        if (RELU) {
            v.x = fmaxf(v.x, 0.f); v.y = fmaxf(v.y, 0.f);
            v.z = fmaxf(v.z, 0.f); v.w = fmaxf(v.w, 0.f);
        }
        *(float4*)&C[(size_t)r * Ndim + c] = v;
    }
}

// ---------------- flash attention, fp32, hd=32, BQ=BKV=64 --------------------
// qkv [N, 768]: q at col h*32, k at 256+h*32, v at 512+h*32. o [N, 256] (nhd).
__global__ __launch_bounds__(256) void attn_kernel(
    const float* __restrict__ qkv, float* __restrict__ o)
{
    __shared__ float Qs[32][68];   // [d][q], pre-scaled
    __shared__ float Ks[32][68];   // [d][kv]
    __shared__ float Vs[64][32];   // [kv][d]
    __shared__ float Ps[64][64];   // probs tile

    const int tid = threadIdx.x;
    const int tx = tid & 15, ty = tid >> 4;
    const int head = blockIdx.y;
    const int q0 = blockIdx.x * 64;
    const int d0 = tx << 1;
    const float scale = 0.17677669529663687f;  // 1/sqrt(32)

#pragma unroll
    for (int it = 0; it < 2; it++) {
        int idx = tid + it * 256;
        int r = idx >> 3, c4 = (idx & 7) << 2;
        float4 v = *(const float4*)&qkv[(size_t)(q0 + r) * H3 + head * HD + c4];
        Qs[c4 + 0][r] = v.x * scale; Qs[c4 + 1][r] = v.y * scale;
        Qs[c4 + 2][r] = v.z * scale; Qs[c4 + 3][r] = v.w * scale;
    }

    float m_r[4], l_r[4], O0[4], O1[4];
#pragma unroll
    for (int i = 0; i < 4; i++) { m_r[i] = -1e30f; l_r[i] = 0.f; O0[i] = 0.f; O1[i] = 0.f; }

    for (int kv0 = 0; kv0 < NATOMS; kv0 += 64) {
        __syncthreads();  // prior PV done (also covers Q-load on first iter)
#pragma unroll
        for (int it = 0; it < 2; it++) {
            int idx = tid + it * 256;
            int r = idx >> 3, c4 = (idx & 7) << 2;
            const float* base = &qkv[(size_t)(kv0 + r) * H3 + head * HD];
            float4 kvv = *(const float4*)(base + HID + c4);
            Ks[c4 + 0][r] = kvv.x; Ks[c4 + 1][r] = kvv.y;
            Ks[c4 + 2][r] = kvv.z; Ks[c4 + 3][r] = kvv.w;
            float4 vv = *(const float4*)(base + 2 * HID + c4);
            *(float4*)&Vs[r][c4] = vv;
        }
        __syncthreads();

        float s[4][4] = {};
#pragma unroll
        for (int d = 0; d < 32; d++) {
            float4 a = *(const float4*)&Qs[d][ty << 2];
            float4 b = *(const float4*)&Ks[d][tx << 2];
            s[0][0] += a.x * b.x; s[0][1] += a.x * b.y; s[0][2] += a.x * b.z; s[0][3] += a.x * b.w;
            s[1][0] += a.y * b.x; s[1][1] += a.y * b.y; s[1][2] += a.y * b.z; s[1][3] += a.y * b.w;
            s[2][0] += a.z * b.x; s[2][1] += a.z * b.y; s[2][2] += a.z * b.z; s[2][3] += a.z * b.w;
            s[3][0] += a.w * b.x; s[3][1] += a.w * b.y; s[3][2] += a.w * b.z; s[3][3] += a.w * b.w;
        }

        // online softmax: each row spans the 16 lanes sharing ty (xor masks 8..1)
#pragma unroll
        for (int i = 0; i < 4; i++) {
            float mt = fmaxf(fmaxf(s[i][0], s[i][1]), fmaxf(s[i][2], s[i][3]));
#pragma unroll
            for (int off = 8; off; off >>= 1)
                mt = fmaxf(mt, __shfl_xor_sync(0xffffffffu, mt, off));
            float mn = fmaxf(m_r[i], mt);
            float alpha = __expf(m_r[i] - mn);
            m_r[i] = mn;
            float4 p;
            p.x = __expf(s[i][0] - mn); p.y = __expf(s[i][1] - mn);
            p.z = __expf(s[i][2] - mn); p.w = __expf(s[i][3] - mn);
            *(float4*)&Ps[(ty << 2) + i][tx << 2] = p;
            float ssum = p.x + p.y + p.z + p.w;
#pragma unroll
            for (int off = 8; off; off >>= 1)
                ssum += __shfl_xor_sync(0xffffffffu, ssum, off);
            l_r[i] = l_r[i] * alpha + ssum;
            O0[i] *= alpha; O1[i] *= alpha;
        }
        __syncthreads();

        // PV: O[r][d0..d0+1] += sum_c P[r][c] * V[c][d]
#pragma unroll 8
        for (int c = 0; c < 64; c++) {
            float2 v = *(const float2*)&Vs[c][d0];
            float p0 = Ps[(ty << 2) + 0][c];
            float p1 = Ps[(ty << 2) + 1][c];
            float p2 = Ps[(ty << 2) + 2][c];
            float p3 = Ps[(ty << 2) + 3][c];
            O0[0] += p0 * v.x; O1[0] += p0 * v.y;
            O0[1] += p1 * v.x; O1[1] += p1 * v.y;
            O0[2] += p2 * v.x; O1[2] += p2 * v.y;
            O0[3] += p3 * v.x; O1[3] += p3 * v.y;
        }
    }

#pragma unroll
    for (int i = 0; i < 4; i++) {
        float inv = 1.f / l_r[i];
        float* op = &o[(size_t)(q0 + (ty << 2) + i) * HID + head * HD + d0];
        op[0] = O0[i] * inv;
        op[1] = O1[i] * inv;
    }
}

// ---------------- LayerNorm(a+b): warp per row, 8 rows per block -------------
__global__ __launch_bounds__(256) void ln_kernel(
    const float* __restrict__ a, const float* __restrict__ b,
    const float* __restrict__ scale, const float* __restrict__ bias,
    float* __restrict__ out)
{
    int row = blockIdx.x * 8 + (threadIdx.x >> 5);
    int lane = threadIdx.x & 31;
    const float* pa = a + (size_t)row * HID;
    const float* pb = b + (size_t)row * HID;

    float v[8];
    float s = 0.f;
#pragma unroll
    for (int j = 0; j < 8; j++) {
        int c = lane + j * 32;
        v[j] = pa[c] + pb[c];
        s += v[j];
    }
#pragma unroll
    for (int off = 16; off; off >>= 1) s += __shfl_xor_sync(0xffffffffu, s, off);
    float mu = s * (1.f / 256.f);
    float q = 0.f;
#pragma unroll
    for (int j = 0; j < 8; j++) { float d = v[j] - mu; q += d * d; }
#pragma unroll
    for (int off = 16; off; off >>= 1) q += __shfl_xor_sync(0xffffffffu, q, off);
    float r = rsqrtf(q * (1.f / 256.f) + 1e-5f);
#pragma unroll
    for (int j = 0; j < 8; j++) {
        int c = lane + j * 32;
        out[(size_t)row * HID + c] = (v[j] - mu) * r * scale[c] + bias[c];
    }
}

// ---------------- neighbor scores + softmax + message, one block per atom ----
__global__ __launch_bounds__(256) void neighbor_kernel(
    const float* __restrict__ h, const float* __restrict__ na_w2,
    const float* __restrict__ na_b2,
    const float* __restrict__ neighbors, const float* __restrict__ edge,
    const float* __restrict__ x1, float* __restrict__ x2)
{
    __shared__ float hs[MBOND][HID];     // 16 KB
    __shared__ float w2s[HID * NHEADS];  // 8 KB
    __shared__ float sc[MBOND][NHEADS];
    __shared__ float wm[MBOND];

    int n = blockIdx.x;
    int tid = threadIdx.x;

    const float* hp = h + (size_t)n * MBOND * HID;
    for (int i = tid; i < MBOND * HID; i += 256) hs[i >> 8][i & 255] = hp[i];
    for (int i = tid; i < HID * NHEADS; i += 256) w2s[i] = na_w2[i];
    __syncthreads();

    if (tid < MBOND * NHEADS) {
        int m = tid >> 3, p = tid & 7;
        float acc = na_b2[p];
#pragma unroll 8
        for (int j = 0; j < HID; j++) acc += hs[m][j] * w2s[j * NHEADS + p];
        sc[m][p] = acc;
    }
    __syncthreads();

    if (tid < NHEADS) {
        int p = tid;
        float mx = -1e30f;
#pragma unroll
        for (int m = 0; m < MBOND; m++) mx = fmaxf(mx, sc[m][p]);
        float e[MBOND], ssum = 0.f;
#pragma unroll
        for (int m = 0; m < MBOND; m++) { e[m] = __expf(sc[m][p] - mx); ssum += e[m]; }
        float inv = 1.f / ssum;
#pragma unroll
        for (int m = 0; m < MBOND; m++) sc[m][p] = e[m] * inv;
    }
    __syncthreads();

    if (tid < MBOND) {
        float ssum = 0.f;
#pragma unroll
        for (int p = 0; p < NHEADS; p++) ssum += sc[tid][p];
        wm[tid] = ssum * (1.f / NHEADS);
    }
    __syncthreads();

    const float* np = neighbors + (size_t)n * MBOND * HID;
    const float* ep = edge + (size_t)n * MBOND * HID;
    float acc = x1[(size_t)n * HID + tid];
#pragma unroll
    for (int m = 0; m < MBOND; m++)
        acc += np[m * HID + tid] * ep[m * HID + tid] * wm[m];
    x2[(size_t)n * HID + tid] = acc;
}

// ---------------- launch ------------------------------------------------------
extern "C" void kernel_launch(void* const* d_in, const int* in_sizes, int n_in,
                              void* d_out, int out_size)
{
    const float* x         = (const float*)d_in[0];
    const float* neighbors = (const float*)d_in[1];
    const float* edge      = (const float*)d_in[2];
    const float* in_w      = (const float*)d_in[3];
    const float* in_b      = (const float*)d_in[4];
    const float* out_w     = (const float*)d_in[5];
    const float* out_b     = (const float*)d_in[6];
    const float* ln1s      = (const float*)d_in[7];
    const float* ln1b      = (const float*)d_in[8];
    const float* na_w1     = (const float*)d_in[9];
    const float* na_b1     = (const float*)d_in[10];
    const float* na_w2     = (const float*)d_in[11];
    const float* na_b2     = (const float*)d_in[12];
    const float* ff_w1     = (const float*)d_in[13];
    const float* ff_b1     = (const float*)d_in[14];
    const float* ff_w2     = (const float*)d_in[15];
    const float* ff_b2     = (const float*)d_in[16];
    const float* ln2s      = (const float*)d_in[17];
    const float* ln2b      = (const float*)d_in[18];
    float* out = (float*)d_out;

    float *qkv, *o, *x1, *t1, *h, *x2, *ffb, *t4;
    cudaGetSymbolAddress((void**)&qkv, g_qkv);
    cudaGetSymbolAddress((void**)&o,   g_o);
    cudaGetSymbolAddress((void**)&x1,  g_x1);
    cudaGetSymbolAddress((void**)&t1,  g_t1);
    cudaGetSymbolAddress((void**)&h,   g_h);
    cudaGetSymbolAddress((void**)&x2,  g_x2);
    cudaGetSymbolAddress((void**)&ffb, g_ff);
    cudaGetSymbolAddress((void**)&t4,  g_t4);

    // 1) qkv = x @ in_proj_w + b       [8192,768]
    sgemm_kernel<false, false><<<dim3(12, 128), 256>>>(x, in_w, in_b, nullptr, qkv, NATOMS, H3, HID);
    // 2) flash attention -> o          [8192,256]
    attn_kernel<<<dim3(128, 8), 256>>>(qkv, o);
    // 3) attn_out = o @ out_proj_w + b -> t4
    sgemm_kernel<false, false><<<dim3(4, 128), 256>>>(o, out_w, out_b, nullptr, t4, NATOMS, HID, HID);
    // 4) x1 = LN1(x + attn_out)
    ln_kernel<<<1024, 256>>>(x, t4, ln1s, ln1b, x1);
    // 5) t1 = x1 @ na_w1[:256] + na_b1
    sgemm_kernel<false, false><<<dim3(4, 128), 256>>>(x1, na_w1, na_b1, nullptr, t1, NATOMS, HID, HID);
    // 6) h = relu(neighbors_flat @ na_w1[256:] + t1[row>>4])   [131072,256]
    sgemm_kernel<true, true><<<dim3(4, 2048), 256>>>(neighbors, na_w1 + HID * HID, nullptr, t1, h,
                                                     NATOMS * MBOND, HID, HID);
    // 7) neighbor softmax + message -> x2
    neighbor_kernel<<<NATOMS, 256>>>(h, na_w2, na_b2, neighbors, edge, x1, x2);
    // 8) ffb = relu(x2 @ ff_w1 + b1)   [8192,1024]
    sgemm_kernel<true, false><<<dim3(16, 128), 256>>>(x2, ff_w1, ff_b1, nullptr, ffb, NATOMS, FFD, HID);
    // 9) t4 = ffb @ ff_w2 + b2
    sgemm_kernel<false, false><<<dim3(4, 128), 256>>>(ffb, ff_w2, ff_b2, nullptr, t4, NATOMS, HID, FFD);
    // 10) out = LN2(x2 + t4)
    ln_kernel<<<1024, 256>>>(x2, t4, ln2s, ln2b, out);
}

// round 2
// speedup vs baseline: 2.6591x; 2.6591x over previous
#include <cuda_runtime.h>
#include <math.h>
#include <stdint.h>

#define NATOMS 8192
#define HID    256
#define MBOND  16
#define NHEADS 8
#define HD     32
#define H3     768
#define FFD    1024

// ---------------- scratch (static device globals; no allocs allowed) ----------
__device__ float g_qkv[NATOMS * H3];
__device__ float g_o  [NATOMS * HID];
__device__ float g_x1 [NATOMS * HID];
__device__ float g_t1 [NATOMS * HID];
__device__ float g_h  [NATOMS * MBOND * HID];
__device__ float g_x2 [NATOMS * HID];
__device__ float g_ff [NATOMS * FFD];
__device__ float g_t4 [NATOMS * HID];

// ---------------- tf32 helpers ------------------------------------------------
__device__ __forceinline__ uint32_t f2tf(float x) {
    uint32_t u;
    asm("cvt.rna.tf32.f32 %0, %1;" : "=r"(u) : "f"(x));
    return u;
}

__device__ __forceinline__ void mma8(float* c, const uint32_t* a, const uint32_t* b) {
    asm volatile(
        "mma.sync.aligned.m16n8k8.row.col.f32.tf32.tf32.f32 "
        "{%0,%1,%2,%3}, {%4,%5,%6,%7}, {%8,%9}, {%0,%1,%2,%3};\n"
        : "+f"(c[0]), "+f"(c[1]), "+f"(c[2]), "+f"(c[3])
        : "r"(a[0]), "r"(a[1]), "r"(a[2]), "r"(a[3]), "r"(b[0]), "r"(b[1]));
}

// ---------------- tf32 MMA GEMM: C = op(A@B (+bias) (+aux[r>>4])) -------------
// A [M,K] row-major fp32, B [K,N] row-major fp32. BM=BN=64, BK=32, 256 thr.
// Warps 2x4 -> warp tile 32x16 -> 2x2 m16n8 mma tiles, 4 k-steps of 8.
template <bool RELU, bool AUX16>
__global__ __launch_bounds__(256) void mma_gemm(
    const float* __restrict__ A, const float* __restrict__ B,
    const float* __restrict__ bias, const float* __restrict__ aux,
    float* __restrict__ C, int Mdim, int Ndim, int Kdim)
{
    __shared__ uint32_t As[64][36];   // tf32 bits, padded: banks (4r+c)%32
    __shared__ uint32_t Bs[32][68];   // tf32 bits, padded: banks (4k+n)%32

    const int tid = threadIdx.x;
    const int lane = tid & 31, warp = tid >> 5;
    const int g = lane >> 2, t = lane & 3;
    const int wm = (warp >> 2) * 32;
    const int wn = (warp & 3) * 16;
    const int rowBase = blockIdx.y * 64;
    const int colBase = blockIdx.x * 64;

    const int ar = tid >> 3, ac4 = (tid & 7) << 2;    // A tile: rows ar, ar+32
    const int br = tid >> 4, bc4 = (tid & 15) << 2;   // B tile: rows br, br+16

    float acc[2][2][4] = {};

    for (int k0 = 0; k0 < Kdim; k0 += 32) {
        __syncthreads();
#pragma unroll
        for (int it = 0; it < 2; it++) {
            float4 av = *(const float4*)&A[(size_t)(rowBase + ar + it * 32) * Kdim + k0 + ac4];
            uint4 au = make_uint4(f2tf(av.x), f2tf(av.y), f2tf(av.z), f2tf(av.w));
            *(uint4*)&As[ar + it * 32][ac4] = au;
            float4 bv = *(const float4*)&B[(size_t)(k0 + br + it * 16) * Ndim + colBase + bc4];
            uint4 bu = make_uint4(f2tf(bv.x), f2tf(bv.y), f2tf(bv.z), f2tf(bv.w));
            *(uint4*)&Bs[br + it * 16][bc4] = bu;
        }
        __syncthreads();

#pragma unroll
        for (int kk = 0; kk < 32; kk += 8) {
            uint32_t af[2][4], bf[2][2];
#pragma unroll
            for (int mi = 0; mi < 2; mi++) {
                int r = wm + mi * 16 + g;
                af[mi][0] = As[r][kk + t];
                af[mi][1] = As[r + 8][kk + t];
                af[mi][2] = As[r][kk + 4 + t];
                af[mi][3] = As[r + 8][kk + 4 + t];
            }
#pragma unroll
            for (int ni = 0; ni < 2; ni++) {
                int c = wn + ni * 8 + g;
                bf[ni][0] = Bs[kk + t][c];
                bf[ni][1] = Bs[kk + 4 + t][c];
            }
#pragma unroll
            for (int mi = 0; mi < 2; mi++)
#pragma unroll
                for (int ni = 0; ni < 2; ni++)
                    mma8(acc[mi][ni], af[mi], bf[ni]);
        }
    }

#pragma unroll
    for (int mi = 0; mi < 2; mi++) {
#pragma unroll
        for (int ni = 0; ni < 2; ni++) {
            int r0 = rowBase + wm + mi * 16 + g;
            int r1 = r0 + 8;
            int c = colBase + wn + ni * 8 + 2 * t;
            float2 v0 = make_float2(acc[mi][ni][0], acc[mi][ni][1]);
            float2 v1 = make_float2(acc[mi][ni][2], acc[mi][ni][3]);
            if (bias) {
                float b0 = bias[c], b1 = bias[c + 1];
                v0.x += b0; v0.y += b1; v1.x += b0; v1.y += b1;
            }
            if (AUX16) {
                const float* a0 = aux + (size_t)(r0 >> 4) * Ndim + c;
                const float* a1 = aux + (size_t)(r1 >> 4) * Ndim + c;
                v0.x += a0[0]; v0.y += a0[1];
                v1.x += a1[0]; v1.y += a1[1];
            }
            if (RELU) {
                v0.x = fmaxf(v0.x, 0.f); v0.y = fmaxf(v0.y, 0.f);
                v1.x = fmaxf(v1.x, 0.f); v1.y = fmaxf(v1.y, 0.f);
            }
            *(float2*)&C[(size_t)r0 * Ndim + c] = v0;
            *(float2*)&C[(size_t)r1 * Ndim + c] = v1;
        }
    }
}

// ---------------- flash attention, tf32 MMA, hd=32, BQ=BKV=64 ----------------
// qkv [N,768]: q at h*32, k at 256+h*32, v at 512+h*32. o [N,256] (n, h*32+d).
__global__ __launch_bounds__(256) void attn_mma(
    const float* __restrict__ qkv, float* __restrict__ o)
{
    __shared__ uint32_t Qs[64][36];   // tf32, pre-scaled
    __shared__ uint32_t Ks[64][36];   // tf32
    __shared__ uint32_t Vs[64][36];   // tf32
    __shared__ uint32_t Ps[64][68];   // S (fp32 bits) then P (tf32 bits)
    __shared__ float m_s[64], l_s[64], al_s[64];

    const int tid = threadIdx.x;
    const int lane = tid & 31, warp = tid >> 5;
    const int g = lane >> 2, t = lane & 3;
    const int head = blockIdx.y;
    const int q0 = blockIdx.x * 64;
    const float scale = 0.17677669529663687f;  // 1/sqrt(32)

    // S-tile warp layout (64x64): warps 2x4
    const int swm = (warp >> 2) * 32;
    const int swn = (warp & 3) * 16;
    // PV warp layout (64x32): warps 4x2
    const int owm = (warp >> 1) * 16;
    const int own = (warp & 1) * 16;

    // load Q tile (scaled, tf32)
    {
        int r = tid >> 3, c4 = (tid & 7) << 2;
#pragma unroll
        for (int it = 0; it < 2; it++) {
            float4 v = *(const float4*)&qkv[(size_t)(q0 + r + it * 32) * H3 + head * HD + c4];
            uint4 u = make_uint4(f2tf(v.x * scale), f2tf(v.y * scale),
                                 f2tf(v.z * scale), f2tf(v.w * scale));
            *(uint4*)&Qs[r + it * 32][c4] = u;
        }
    }
    if (tid < 64) { m_s[tid] = -1e30f; l_s[tid] = 0.f; }

    float oacc[2][4] = {};

    for (int kv0 = 0; kv0 < NATOMS; kv0 += 64) {
        __syncthreads();  // (a) prev PV done; Q load done on first iter
        {
            int r = tid >> 3, c4 = (tid & 7) << 2;
#pragma unroll
            for (int it = 0; it < 2; it++) {
                const float* base = &qkv[(size_t)(kv0 + r + it * 32) * H3 + head * HD];
                float4 kvv = *(const float4*)(base + HID + c4);
                *(uint4*)&Ks[r + it * 32][c4] =
                    make_uint4(f2tf(kvv.x), f2tf(kvv.y), f2tf(kvv.z), f2tf(kvv.w));
                float4 vv = *(const float4*)(base + 2 * HID + c4);
                *(uint4*)&Vs[r + it * 32][c4] =
                    make_uint4(f2tf(vv.x), f2tf(vv.y), f2tf(vv.z), f2tf(vv.w));
            }
        }
        __syncthreads();  // (b) tiles ready

        // ---- S = Q @ K^T (64x64, k=32) ----
        float sacc[2][2][4] = {};
#pragma unroll
        for (int kk = 0; kk < 32; kk += 8) {
            uint32_t af[2][4], bf[2][2];
#pragma unroll
            for (int mi = 0; mi < 2; mi++) {
                int r = swm + mi * 16 + g;
                af[mi][0] = Qs[r][kk + t];
                af[mi][1] = Qs[r + 8][kk + t];
                af[mi][2] = Qs[r][kk + 4 + t];
                af[mi][3] = Qs[r + 8][kk + 4 + t];
            }
#pragma unroll
            for (int ni = 0; ni < 2; ni++) {
                int c = swn + ni * 8 + g;
                bf[ni][0] = Ks[c][kk + t];
                bf[ni][1] = Ks[c][kk + 4 + t];
            }
#pragma unroll
            for (int mi = 0; mi < 2; mi++)
#pragma unroll
                for (int ni = 0; ni < 2; ni++)
                    mma8(sacc[mi][ni], af[mi], bf[ni]);
        }
        // spill S to smem (fp32 bits)
#pragma unroll
        for (int mi = 0; mi < 2; mi++)
#pragma unroll
            for (int ni = 0; ni < 2; ni++) {
                int r = swm + mi * 16 + g;
                int c = swn + ni * 8 + 2 * t;
                Ps[r][c]     = __float_as_uint(sacc[mi][ni][0]);
                Ps[r][c + 1] = __float_as_uint(sacc[mi][ni][1]);
                Ps[r + 8][c]     = __float_as_uint(sacc[mi][ni][2]);
                Ps[r + 8][c + 1] = __float_as_uint(sacc[mi][ni][3]);
            }
        __syncthreads();  // (c) S visible

        // ---- online softmax: 4 threads/row, interleaved cols (bank-clean) ----
        {
            int row = tid >> 2, q = tid & 3;
            float sv[16];
            float mx = -1e30f;
#pragma unroll
            for (int j = 0; j < 16; j++) {
                sv[j] = __uint_as_float(Ps[row][q + 4 * j]);
                mx = fmaxf(mx, sv[j]);
            }
            mx = fmaxf(mx, __shfl_xor_sync(0xffffffffu, mx, 1));
            mx = fmaxf(mx, __shfl_xor_sync(0xffffffffu, mx, 2));
            float mold = m_s[row];
            float mn = fmaxf(mold, mx);
            float alpha = __expf(mold - mn);
            float sum = 0.f;
#pragma unroll
            for (int j = 0; j < 16; j++) {
                float p = __expf(sv[j] - mn);
                Ps[row][q + 4 * j] = f2tf(p);
                sum += p;
            }
            sum += __shfl_xor_sync(0xffffffffu, sum, 1);
            sum += __shfl_xor_sync(0xffffffffu, sum, 2);
            if (q == 0) {
                l_s[row] = l_s[row] * alpha + sum;
                m_s[row] = mn;
                al_s[row] = alpha;
            }
        }
        __syncthreads();  // (d) P + stats ready

        // ---- O = O*alpha + P @ V (64x32, k=64) ----
        {
            float a0 = al_s[owm + g];
            float a1 = al_s[owm + 8 + g];
#pragma unroll
            for (int ni = 0; ni < 2; ni++) {
                oacc[ni][0] *= a0; oacc[ni][1] *= a0;
                oacc[ni][2] *= a1; oacc[ni][3] *= a1;
            }
        }
#pragma unroll
        for (int kk = 0; kk < 64; kk += 8) {
            uint32_t af[4], bf[2][2];
            af[0] = Ps[owm + g][kk + t];
            af[1] = Ps[owm + 8 + g][kk + t];
            af[2] = Ps[owm + g][kk + 4 + t];
            af[3] = Ps[owm + 8 + g][kk + 4 + t];
#pragma unroll
            for (int ni = 0; ni < 2; ni++) {
                int c = own + ni * 8 + g;
                bf[ni][0] = Vs[kk + t][c];
                bf[ni][1] = Vs[kk + 4 + t][c];
            }
#pragma unroll
            for (int ni = 0; ni < 2; ni++)
                mma8(oacc[ni], af, bf[ni]);
        }
    }

    // final normalize + write
    {
        float inv0 = 1.f / l_s[owm + g];
        float inv1 = 1.f / l_s[owm + 8 + g];
#pragma unroll
        for (int ni = 0; ni < 2; ni++) {
            int c = own + ni * 8 + 2 * t;
            float* p0 = &o[(size_t)(q0 + owm + g) * HID + head * HD + c];
            float* p1 = &o[(size_t)(q0 + owm + 8 + g) * HID + head * HD + c];
            *(float2*)p0 = make_float2(oacc[ni][0] * inv0, oacc[ni][1] * inv0);
            *(float2*)p1 = make_float2(oacc[ni][2] * inv1, oacc[ni][3] * inv1);
        }
    }
}

// ---------------- LayerNorm(a+b): warp per row, 8 rows per block -------------
__global__ __launch_bounds__(256) void ln_kernel(
    const float* __restrict__ a, const float* __restrict__ b,
    const float* __restrict__ scale, const float* __restrict__ bias,
    float* __restrict__ out)
{
    int row = blockIdx.x * 8 + (threadIdx.x >> 5);
    int lane = threadIdx.x & 31;
    const float* pa = a + (size_t)row * HID;
    const float* pb = b + (size_t)row * HID;

    float v[8];
    float s = 0.f;
#pragma unroll
    for (int j = 0; j < 8; j++) {
        int c = lane + j * 32;
        v[j] = pa[c] + pb[c];
        s += v[j];
    }
#pragma unroll
    for (int off = 16; off; off >>= 1) s += __shfl_xor_sync(0xffffffffu, s, off);
    float mu = s * (1.f / 256.f);
    float q = 0.f;
#pragma unroll
    for (int j = 0; j < 8; j++) { float d = v[j] - mu; q += d * d; }
#pragma unroll
    for (int off = 16; off; off >>= 1) q += __shfl_xor_sync(0xffffffffu, q, off);
    float r = rsqrtf(q * (1.f / 256.f) + 1e-5f);
#pragma unroll
    for (int j = 0; j < 8; j++) {
        int c = lane + j * 32;
        out[(size_t)row * HID + c] = (v[j] - mu) * r * scale[c] + bias[c];
    }
}

// ---------------- neighbor scores + softmax + message, one block per atom ----
__global__ __launch_bounds__(256) void neighbor_kernel(
    const float* __restrict__ h, const float* __restrict__ na_w2,
    const float* __restrict__ na_b2,
    const float* __restrict__ neighbors, const float* __restrict__ edge,
    const float* __restrict__ x1, float* __restrict__ x2)
{
    __shared__ float hs[MBOND][HID];
    __shared__ float w2s[HID * NHEADS];
    __shared__ float sc[MBOND][NHEADS];
    __shared__ float wm[MBOND];

    int n = blockIdx.x;
    int tid = threadIdx.x;

    const float* hp = h + (size_t)n * MBOND * HID;
    for (int i = tid; i < MBOND * HID; i += 256) hs[i >> 8][i & 255] = hp[i];
    for (int i = tid; i < HID * NHEADS; i += 256) w2s[i] = na_w2[i];
    __syncthreads();

    if (tid < MBOND * NHEADS) {
        int m = tid >> 3, p = tid & 7;
        float acc = na_b2[p];
#pragma unroll 8
        for (int j = 0; j < HID; j++) acc += hs[m][j] * w2s[j * NHEADS + p];
        sc[m][p] = acc;
    }
    __syncthreads();

    if (tid < NHEADS) {
        int p = tid;
        float mx = -1e30f;
#pragma unroll
        for (int m = 0; m < MBOND; m++) mx = fmaxf(mx, sc[m][p]);
        float e[MBOND], ssum = 0.f;
#pragma unroll
        for (int m = 0; m < MBOND; m++) { e[m] = __expf(sc[m][p] - mx); ssum += e[m]; }
        float inv = 1.f / ssum;
#pragma unroll
        for (int m = 0; m < MBOND; m++) sc[m][p] = e[m] * inv;
    }
    __syncthreads();

    if (tid < MBOND) {
        float ssum = 0.f;
#pragma unroll
        for (int p = 0; p < NHEADS; p++) ssum += sc[tid][p];
        wm[tid] = ssum * (1.f / NHEADS);
    }
    __syncthreads();

    const float* np = neighbors + (size_t)n * MBOND * HID;
    const float* ep = edge + (size_t)n * MBOND * HID;
    float acc = x1[(size_t)n * HID + tid];
#pragma unroll
    for (int m = 0; m < MBOND; m++)
        acc += np[m * HID + tid] * ep[m * HID + tid] * wm[m];
    x2[(size_t)n * HID + tid] = acc;
}

// ---------------- launch ------------------------------------------------------
extern "C" void kernel_launch(void* const* d_in, const int* in_sizes, int n_in,
                              void* d_out, int out_size)
{
    const float* x         = (const float*)d_in[0];
    const float* neighbors = (const float*)d_in[1];
    const float* edge      = (const float*)d_in[2];
    const float* in_w      = (const float*)d_in[3];
    const float* in_b      = (const float*)d_in[4];
    const float* out_w     = (const float*)d_in[5];
    const float* out_b     = (const float*)d_in[6];
    const float* ln1s      = (const float*)d_in[7];
    const float* ln1b      = (const float*)d_in[8];
    const float* na_w1     = (const float*)d_in[9];
    const float* na_b1     = (const float*)d_in[10];
    const float* na_w2     = (const float*)d_in[11];
    const float* na_b2     = (const float*)d_in[12];
    const float* ff_w1     = (const float*)d_in[13];
    const float* ff_b1     = (const float*)d_in[14];
    const float* ff_w2     = (const float*)d_in[15];
    const float* ff_b2     = (const float*)d_in[16];
    const float* ln2s      = (const float*)d_in[17];
    const float* ln2b      = (const float*)d_in[18];
    float* out = (float*)d_out;

    float *qkv, *o, *x1, *t1, *h, *x2, *ffb, *t4;
    cudaGetSymbolAddress((void**)&qkv, g_qkv);
    cudaGetSymbolAddress((void**)&o,   g_o);
    cudaGetSymbolAddress((void**)&x1,  g_x1);
    cudaGetSymbolAddress((void**)&t1,  g_t1);
    cudaGetSymbolAddress((void**)&h,   g_h);
    cudaGetSymbolAddress((void**)&x2,  g_x2);
    cudaGetSymbolAddress((void**)&ffb, g_ff);
    cudaGetSymbolAddress((void**)&t4,  g_t4);

    // 1) qkv = x @ in_proj_w + b       [8192,768]
    mma_gemm<false, false><<<dim3(12, 128), 256>>>(x, in_w, in_b, nullptr, qkv, NATOMS, H3, HID);
    // 2) flash attention -> o          [8192,256]
    attn_mma<<<dim3(128, 8), 256>>>(qkv, o);
    // 3) attn_out = o @ out_proj_w + b -> t4
    mma_gemm<false, false><<<dim3(4, 128), 256>>>(o, out_w, out_b, nullptr, t4, NATOMS, HID, HID);
    // 4) x1 = LN1(x + attn_out)
    ln_kernel<<<1024, 256>>>(x, t4, ln1s, ln1b, x1);
    // 5) t1 = x1 @ na_w1[:256] + na_b1
    mma_gemm<false, false><<<dim3(4, 128), 256>>>(x1, na_w1, na_b1, nullptr, t1, NATOMS, HID, HID);
    // 6) h = relu(neighbors_flat @ na_w1[256:] + t1[row>>4])   [131072,256]
    mma_gemm<true, true><<<dim3(4, 2048), 256>>>(neighbors, na_w1 + HID * HID, nullptr, t1, h,
                                                 NATOMS * MBOND, HID, HID);
    // 7) neighbor softmax + message -> x2
    neighbor_kernel<<<NATOMS, 256>>>(h, na_w2, na_b2, neighbors, edge, x1, x2);
    // 8) ffb = relu(x2 @ ff_w1 + b1)   [8192,1024]
    mma_gemm<true, false><<<dim3(16, 128), 256>>>(x2, ff_w1, ff_b1, nullptr, ffb, NATOMS, FFD, HID);
    // 9) t4 = ffb @ ff_w2 + b2
    mma_gemm<false, false><<<dim3(4, 128), 256>>>(ffb, ff_w2, ff_b2, nullptr, t4, NATOMS, HID, FFD);
    // 10) out = LN2(x2 + t4)
    ln_kernel<<<1024, 256>>>(x2, t4, ln2s, ln2b, out);
}